// round 11
// baseline (speedup 1.0000x reference)
#include <cuda_runtime.h>
#include <math.h>

// Problem constants
#define BB 4
#define SS 256
#define NN 512
#define RR 32
#define LL (NN * RR)          // 16384 output samples per batch
#define NCHUNK 8
#define S_PER_CHUNK (SS / NCHUNK)  // 32
#define NE 513                // extended segments: head(1) + 511 mids + tail
#define NQ2 257               // ceil(513/2) segment-pairs per batch

// Reference-matching constants
#define TWO_PI_D 6.283185307179586
#define CF_F  ((float)(TWO_PI_D / 44100.0))
#define CMOD_F ((float)TWO_PI_D)
#define INV_CMOD_F ((float)(1.0 / (double)((float)TWO_PI_D)))

// Scratch — TRANSPOSED layout: [b][e][s] so k_main staging is coalesced.
__device__ float4 d_tab[BB * NE * SS];       // {base_mod, g, dg/64, a}
__device__ float  d_da [BB * NE * SS];       // a_{i+1}-a_i

// ---------------------------------------------------------------------------
// double-float helpers (all-fp32 compensated arithmetic)
// ---------------------------------------------------------------------------
__device__ __forceinline__ float2 two_sum(float a, float b) {
    float s  = a + b;
    float bb = s - a;
    float e  = (a - (s - bb)) + (b - bb);
    return make_float2(s, e);
}
__device__ __forceinline__ float2 df_add(float2 a, float2 b) {
    float2 s = two_sum(a.x, b.x);
    float lo = s.y + (a.y + b.y);
    float hi = s.x + lo;
    lo = lo - (hi - s.x);
    return make_float2(hi, lo);
}

// ---------------------------------------------------------------------------
// Kernel 1: df-precision prefix of omegas -> per-segment fp32 table,
// written TRANSPOSED ([b][e][s]). Writes are scattered 16B sectors, but
// stores are fire-and-forget into L2 — no latency exposure.
// ---------------------------------------------------------------------------
__global__ void k_base(const float* __restrict__ freq,
                       const float* __restrict__ amp) {
    int seq  = blockIdx.x;          // b*SS + s
    int b    = seq >> 8;            // SS = 256
    int s    = seq & (SS - 1);
    int i    = threadIdx.x;
    int lane = i & 31;
    int wid  = i >> 5;

    float f = freq[seq * NN + i];
    float a = amp [seq * NN + i];

    float g_hi = f * CF_F;
    float g_lo = fmaf(f, CF_F, -g_hi);      // exact product tail
    float2 x = make_float2(g_hi, g_lo);

    #pragma unroll
    for (int off = 1; off < 32; off <<= 1) {
        float yh = __shfl_up_sync(0xFFFFFFFFu, x.x, off);
        float yl = __shfl_up_sync(0xFFFFFFFFu, x.y, off);
        if (lane >= off) x = df_add(x, make_float2(yh, yl));
    }

    __shared__ float2 wsum[16];
    if (lane == 31) wsum[wid] = x;
    __syncthreads();
    if (wid == 0) {
        float2 y = (lane < 16) ? wsum[lane] : make_float2(0.0f, 0.0f);
        #pragma unroll
        for (int off = 1; off < 16; off <<= 1) {
            float zh = __shfl_up_sync(0xFFFFFFFFu, y.x, off);
            float zl = __shfl_up_sync(0xFFFFFFFFu, y.y, off);
            if (lane >= off) y = df_add(y, make_float2(zh, zl));
        }
        if (lane < 16) wsum[lane] = y;
    }
    __syncthreads();
    float2 Q = x;
    if (wid > 0) Q = df_add(Q, wsum[wid - 1]);

    float2 Q32  = make_float2(32.0f * Q.x, 32.0f * Q.y);
    float2 g16n = make_float2(-16.0f * g_hi, -16.0f * g_lo);
    float2 P = df_add(Q32, g16n);

    float q = floorf(P.x * INV_CMOD_F);
    float m = fmaf(-q, CMOD_F, P.x) + P.y;

    float fnext = (i < NN - 1) ? freq[seq * NN + i + 1] : f;
    float anext = (i < NN - 1) ? amp [seq * NN + i + 1] : a;
    float dg64 = (i < NN - 1) ? (fnext * CF_F - g_hi) * (1.0f / 64.0f) : 0.0f;
    float da   = (i < NN - 1) ? (anext - a) : 0.0f;

    size_t idx = ((size_t)b * NE + (i + 1)) * SS + s;   // transposed
    d_tab[idx] = make_float4(m, g_hi, dg64, a);
    d_da [idx] = da;
    if (i == 0) {                       // head segment e=0
        size_t idx0 = ((size_t)b * NE) * SS + s;
        d_tab[idx0] = make_float4(0.0f, g_hi, 0.0f, a);
        d_da [idx0] = 0.0f;
    }
}

// ---------------------------------------------------------------------------
// Kernel 2: synthesis with coalesced SMEM staging (table is [b][e][s]).
// Block covers one (batch, segment-pair) for all 256 sines; staging is two
// block-wide fully-coalesced float4 reads + two float reads. Inner loop
// identical to round 9 (bit-identical results, same summation order).
// ---------------------------------------------------------------------------
__global__ void __launch_bounds__(256, 4) k_main(float* __restrict__ out) {
    int tid  = threadIdx.x;
    int c    = tid >> 5;            // sine chunk 0..7
    int lane = tid & 31;
    int seg2 = lane >> 4;           // local segment 0..1
    int jg   = lane & 15;           // samples j = jg, jg+16

    int q = blockIdx.x % NQ2;       // segment pair
    int b = blockIdx.x / NQ2;
    int e0  = 2 * q;
    int e0c = (e0     > NE - 1) ? (NE - 1) : e0;
    int e1c = (e0 + 1 > NE - 1) ? (NE - 1) : (e0 + 1);

    // ---- coalesced staging: 256 sines x 2 segments ----
    __shared__ float4 stab0[SS];    // 4 KB  (segment e0)
    __shared__ float4 stab1[SS];    // 4 KB  (segment e0+1)
    __shared__ float  sda0 [SS];    // 1 KB
    __shared__ float  sda1 [SS];    // 1 KB
    {
        size_t base0 = ((size_t)b * NE + e0c) * SS + tid;
        size_t base1 = ((size_t)b * NE + e1c) * SS + tid;
        stab0[tid] = d_tab[base0];
        stab1[tid] = d_tab[base1];
        sda0 [tid] = d_da [base0];
        sda1 [tid] = d_da [base1];
    }
    __syncthreads();

    const float4* myTab = seg2 ? stab1 : stab0;
    const float*  myDa  = seg2 ? sda1  : sda0;

    float u0 = (float)(jg + 1);
    float u1 = u0 + 16.0f;
    float s0 = u0 * u0, s1 = u1 * u1;
    float w0 = (float)(2 * jg + 1) * (1.0f / 64.0f);
    float w1 = w0 + 0.5f;

    int sbase = c * S_PER_CHUNK;
    float a0 = 0.0f, a1 = 0.0f;

    #pragma unroll
    for (int k = 0; k < S_PER_CHUNK; k += 4) {
        float4 v0 = myTab[sbase + k    ];
        float4 v1 = myTab[sbase + k + 1];
        float4 v2 = myTab[sbase + k + 2];
        float4 v3 = myTab[sbase + k + 3];
        float  d0 = myDa [sbase + k    ];
        float  d1 = myDa [sbase + k + 1];
        float  d2 = myDa [sbase + k + 2];
        float  d3 = myDa [sbase + k + 3];

        float p00 = fmaf(s0, v0.z, fmaf(u0, v0.y, v0.x));
        float p01 = fmaf(s1, v0.z, fmaf(u1, v0.y, v0.x));
        float p10 = fmaf(s0, v1.z, fmaf(u0, v1.y, v1.x));
        float p11 = fmaf(s1, v1.z, fmaf(u1, v1.y, v1.x));
        float p20 = fmaf(s0, v2.z, fmaf(u0, v2.y, v2.x));
        float p21 = fmaf(s1, v2.z, fmaf(u1, v2.y, v2.x));
        float p30 = fmaf(s0, v3.z, fmaf(u0, v3.y, v3.x));
        float p31 = fmaf(s1, v3.z, fmaf(u1, v3.y, v3.x));

        float m00 = fmaf(w0, d0, v0.w);
        float m01 = fmaf(w1, d0, v0.w);
        float m10 = fmaf(w0, d1, v1.w);
        float m11 = fmaf(w1, d1, v1.w);
        float m20 = fmaf(w0, d2, v2.w);
        float m21 = fmaf(w1, d2, v2.w);
        float m30 = fmaf(w0, d3, v3.w);
        float m31 = fmaf(w1, d3, v3.w);

        a0 = fmaf(m00, __sinf(p00), a0);
        a1 = fmaf(m01, __sinf(p01), a1);
        a0 = fmaf(m10, __sinf(p10), a0);
        a1 = fmaf(m11, __sinf(p11), a1);
        a0 = fmaf(m20, __sinf(p20), a0);
        a1 = fmaf(m21, __sinf(p21), a1);
        a0 = fmaf(m30, __sinf(p30), a0);
        a1 = fmaf(m31, __sinf(p31), a1);
    }

    __shared__ float sred[NCHUNK][2 * 33];
    int base = seg2 * 33 + jg;
    sred[c][base     ] = a0;
    sred[c][base + 16] = a1;
    __syncthreads();

    if (tid < 64) {
        int e_loc = tid >> 5;           // 0..1
        int j     = tid & 31;
        int e_out = 2 * q + e_loc;
        float s = 0.0f;
        #pragma unroll
        for (int cc = 0; cc < NCHUNK; cc++) s += sred[cc][e_loc * 33 + j];

        bool valid = (e_out <= NE - 1);
        if (e_out == 0 || e_out == NE - 1) valid = valid && (j < 16);
        if (valid) {
            int t = (e_out == 0) ? j : 16 + 32 * (e_out - 1) + j;
            out[b * LL + t] = s;
        }
    }
}

// ---------------------------------------------------------------------------
extern "C" void kernel_launch(void* const* d_in, const int* in_sizes, int n_in,
                              void* d_out, int out_size) {
    const float* freq = (const float*)d_in[0];
    const float* amp  = (const float*)d_in[1];
    float* out = (float*)d_out;

    k_base<<<BB * SS, NN>>>(freq, amp);        // 1024 blocks x 512
    k_main<<<BB * NQ2, 256>>>(out);            // 1028 blocks x 256
}

// round 12
// speedup vs baseline: 1.0884x; 1.0884x over previous
#include <cuda_runtime.h>
#include <math.h>

// Problem constants
#define BB 4
#define SS 256
#define NN 512
#define RR 32
#define LL (NN * RR)          // 16384 output samples per batch
#define NCHUNK 8
#define S_PER_CHUNK (SS / NCHUNK)  // 32
#define NE 513                // extended segments: head(1) + 511 mids + tail
#define NQ2 257               // ceil(513/2) segment-pairs per batch

// Reference-matching constants
#define TWO_PI_D 6.283185307179586
#define CF_F  ((float)(TWO_PI_D / 44100.0))
#define CMOD_F ((float)TWO_PI_D)
#define INV_CMOD_F ((float)(1.0 / (double)((float)TWO_PI_D)))

// Scratch — R9 layout: [seq][e] (k_base writes coalesced)
__device__ float4 d_tab[BB * SS * NE];       // {base_mod, g, dg/64, a}
__device__ float  d_da [BB * SS * NE];       // a_{i+1}-a_i

// ---------------------------------------------------------------------------
// packed fp32x2 helpers (Blackwell fma.rn.f32x2 — one FFMA2 = 2 fp32 FMAs)
// ---------------------------------------------------------------------------
typedef unsigned long long ull;
__device__ __forceinline__ ull fma_x2(ull a, ull b, ull c) {
    ull d;
    asm("fma.rn.f32x2 %0, %1, %2, %3;" : "=l"(d) : "l"(a), "l"(b), "l"(c));
    return d;
}
__device__ __forceinline__ ull pack2(float lo, float hi) {
    ull d;
    asm("mov.b64 %0, {%1, %2};" : "=l"(d) : "f"(lo), "f"(hi));
    return d;
}
__device__ __forceinline__ void unpack2(ull v, float& lo, float& hi) {
    asm("mov.b64 {%0, %1}, %2;" : "=f"(lo), "=f"(hi) : "l"(v));
}

// ---------------------------------------------------------------------------
// double-float helpers (all-fp32 compensated arithmetic)
// ---------------------------------------------------------------------------
__device__ __forceinline__ float2 two_sum(float a, float b) {
    float s  = a + b;
    float bb = s - a;
    float e  = (a - (s - bb)) + (b - bb);
    return make_float2(s, e);
}
__device__ __forceinline__ float2 df_add(float2 a, float2 b) {
    float2 s = two_sum(a.x, b.x);
    float lo = s.y + (a.y + b.y);
    float hi = s.x + lo;
    lo = lo - (hi - s.x);
    return make_float2(hi, lo);
}

// ---------------------------------------------------------------------------
// Kernel 1: df-precision prefix of omegas -> per-segment fp32 table,
// [seq][e] layout (coalesced writes). Base phase reduced mod fl32(2*pi):
// hot-loop phase stays in [0,~30) for MUFU.SIN's HW range reduction.
// ---------------------------------------------------------------------------
__global__ void k_base(const float* __restrict__ freq,
                       const float* __restrict__ amp) {
    int seq  = blockIdx.x;
    int i    = threadIdx.x;
    int lane = i & 31;
    int wid  = i >> 5;

    float f = freq[seq * NN + i];
    float a = amp [seq * NN + i];

    float g_hi = f * CF_F;
    float g_lo = fmaf(f, CF_F, -g_hi);      // exact product tail
    float2 x = make_float2(g_hi, g_lo);

    #pragma unroll
    for (int off = 1; off < 32; off <<= 1) {
        float yh = __shfl_up_sync(0xFFFFFFFFu, x.x, off);
        float yl = __shfl_up_sync(0xFFFFFFFFu, x.y, off);
        if (lane >= off) x = df_add(x, make_float2(yh, yl));
    }

    __shared__ float2 wsum[16];
    if (lane == 31) wsum[wid] = x;
    __syncthreads();
    if (wid == 0) {
        float2 y = (lane < 16) ? wsum[lane] : make_float2(0.0f, 0.0f);
        #pragma unroll
        for (int off = 1; off < 16; off <<= 1) {
            float zh = __shfl_up_sync(0xFFFFFFFFu, y.x, off);
            float zl = __shfl_up_sync(0xFFFFFFFFu, y.y, off);
            if (lane >= off) y = df_add(y, make_float2(zh, zl));
        }
        if (lane < 16) wsum[lane] = y;
    }
    __syncthreads();
    float2 Q = x;
    if (wid > 0) Q = df_add(Q, wsum[wid - 1]);

    float2 Q32  = make_float2(32.0f * Q.x, 32.0f * Q.y);
    float2 g16n = make_float2(-16.0f * g_hi, -16.0f * g_lo);
    float2 P = df_add(Q32, g16n);

    float q = floorf(P.x * INV_CMOD_F);
    float m = fmaf(-q, CMOD_F, P.x) + P.y;

    float fnext = (i < NN - 1) ? freq[seq * NN + i + 1] : f;
    float anext = (i < NN - 1) ? amp [seq * NN + i + 1] : a;
    float dg64 = (i < NN - 1) ? (fnext * CF_F - g_hi) * (1.0f / 64.0f) : 0.0f;
    float da   = (i < NN - 1) ? (anext - a) : 0.0f;

    size_t tb = (size_t)seq * NE;
    d_tab[tb + i + 1] = make_float4(m, g_hi, dg64, a);
    d_da [tb + i + 1] = da;
    if (i == 0) {
        d_tab[tb] = make_float4(0.0f, g_hi, 0.0f, a);
        d_da [tb] = 0.0f;
    }
}

// ---------------------------------------------------------------------------
// Kernel 2: synthesis with SoA smem staging + packed f32x2 FMAs.
// Block = one (batch, segment-pair) x all 256 sines. Staging repacks the
// table into sine-pair SoA float2 arrays; the inner loop then runs
// fma.rn.f32x2 on pre-packed operands: per sine-pair-per-sample only
// 2 FFMA2 (phase) + 1 FFMA2 (amp) + 1 FFMA2 (acc) + 2 MUFU.
// Fixed-order smem reduction => deterministic.
// ---------------------------------------------------------------------------
__global__ void __launch_bounds__(256, 4) k_main(float* __restrict__ out) {
    int tid  = threadIdx.x;
    int c    = tid >> 5;            // sine chunk 0..7
    int lane = tid & 31;
    int seg2 = lane >> 4;           // local segment 0..1
    int jg   = lane & 15;           // samples j = jg, jg+16

    int q = blockIdx.x % NQ2;       // segment pair
    int b = blockIdx.x / NQ2;
    int e0  = 2 * q;
    int e0c = (e0     > NE - 1) ? (NE - 1) : e0;
    int e1c = (e0 + 1 > NE - 1) ? (NE - 1) : (e0 + 1);

    // ---- stage into SoA float2 (sine-pair packed) arrays ----
    __shared__ float2 sb[2][SS / 2];   // base
    __shared__ float2 sg[2][SS / 2];   // g
    __shared__ float2 sh[2][SS / 2];   // dg/64
    __shared__ float2 sa[2][SS / 2];   // a
    __shared__ float2 sd[2][SS / 2];   // da
    {
        const float4* row  = d_tab + (size_t)(b * SS + tid) * NE;
        const float*  drow = d_da  + (size_t)(b * SS + tid) * NE;
        float4 v0 = __ldg(row + e0c);
        float4 v1 = __ldg(row + e1c);
        float  d0 = __ldg(drow + e0c);
        float  d1 = __ldg(drow + e1c);
        int hp = tid >> 1, lo = tid & 1;
        ((float*)&sb[0][hp])[lo] = v0.x;  ((float*)&sb[1][hp])[lo] = v1.x;
        ((float*)&sg[0][hp])[lo] = v0.y;  ((float*)&sg[1][hp])[lo] = v1.y;
        ((float*)&sh[0][hp])[lo] = v0.z;  ((float*)&sh[1][hp])[lo] = v1.z;
        ((float*)&sa[0][hp])[lo] = v0.w;  ((float*)&sa[1][hp])[lo] = v1.w;
        ((float*)&sd[0][hp])[lo] = d0;    ((float*)&sd[1][hp])[lo] = d1;
    }
    __syncthreads();

    float u0f = (float)(jg + 1);
    float u1f = u0f + 16.0f;
    float w0f = (float)(2 * jg + 1) * (1.0f / 64.0f);
    float w1f = w0f + 0.5f;

    ull U0 = pack2(u0f, u0f),            U1 = pack2(u1f, u1f);
    ull S0 = pack2(u0f * u0f, u0f * u0f), S1 = pack2(u1f * u1f, u1f * u1f);
    ull W0 = pack2(w0f, w0f),            W1 = pack2(w1f, w1f);

    const ull* pb = (const ull*)sb[seg2];
    const ull* pg = (const ull*)sg[seg2];
    const ull* ph = (const ull*)sh[seg2];
    const ull* pa = (const ull*)sa[seg2];
    const ull* pd = (const ull*)sd[seg2];

    int kbase = c * (S_PER_CHUNK / 2);   // 16 sine-pairs per chunk
    ull acc0 = pack2(0.0f, 0.0f);
    ull acc1 = acc0;

    #pragma unroll
    for (int k = 0; k < S_PER_CHUNK / 2; k++) {
        ull b2 = pb[kbase + k];
        ull g2 = pg[kbase + k];
        ull h2 = ph[kbase + k];
        ull a2 = pa[kbase + k];
        ull d2 = pd[kbase + k];

        ull p20 = fma_x2(S0, h2, fma_x2(U0, g2, b2));
        ull p21 = fma_x2(S1, h2, fma_x2(U1, g2, b2));
        ull m20 = fma_x2(W0, d2, a2);
        ull m21 = fma_x2(W1, d2, a2);

        float x0, x1, y0, y1;
        unpack2(p20, x0, x1);
        unpack2(p21, y0, y1);
        ull sin20 = pack2(__sinf(x0), __sinf(x1));
        ull sin21 = pack2(__sinf(y0), __sinf(y1));

        acc0 = fma_x2(m20, sin20, acc0);
        acc1 = fma_x2(m21, sin21, acc1);
    }

    float a0lo, a0hi, a1lo, a1hi;
    unpack2(acc0, a0lo, a0hi);
    unpack2(acc1, a1lo, a1hi);
    float a0 = a0lo + a0hi;      // even-sines + odd-sines partial
    float a1 = a1lo + a1hi;

    __shared__ float sred[NCHUNK][2 * 33];
    int base = seg2 * 33 + jg;
    sred[c][base     ] = a0;
    sred[c][base + 16] = a1;
    __syncthreads();

    if (tid < 64) {
        int e_loc = tid >> 5;           // 0..1
        int j     = tid & 31;
        int e_out = 2 * q + e_loc;
        float s = 0.0f;
        #pragma unroll
        for (int cc = 0; cc < NCHUNK; cc++) s += sred[cc][e_loc * 33 + j];

        bool valid = (e_out <= NE - 1);
        if (e_out == 0 || e_out == NE - 1) valid = valid && (j < 16);
        if (valid) {
            int t = (e_out == 0) ? j : 16 + 32 * (e_out - 1) + j;
            out[b * LL + t] = s;
        }
    }
}

// ---------------------------------------------------------------------------
extern "C" void kernel_launch(void* const* d_in, const int* in_sizes, int n_in,
                              void* d_out, int out_size) {
    const float* freq = (const float*)d_in[0];
    const float* amp  = (const float*)d_in[1];
    float* out = (float*)d_out;

    k_base<<<BB * SS, NN>>>(freq, amp);        // 1024 blocks x 512
    k_main<<<BB * NQ2, 256>>>(out);            // 1028 blocks x 256
}